// round 5
// baseline (speedup 1.0000x reference)
#include <cuda_runtime.h>
#include <math.h>
#include <stdint.h>

#define BMAX 4096
#define Mc   64
#define Dc   512
#define DOUTc 256
#define NHc  8

// ---------------- scratch (device globals; no allocations) ----------------
__device__ __align__(16) float g_qvec[Dc];
__device__ __align__(16) float g_qk[NHc * Dc];
__device__ __align__(16) float g_cbias[Dc];
__device__ __align__(16) float g_Uattn[(size_t)BMAX * NHc * Dc];  // tf32-rounded
__device__ __align__(16) float g_CTX[(size_t)BMAX * Dc];          // tf32-rounded
__device__ __align__(16) float g_Z[(size_t)BMAX * Dc];            // fp32
__device__ __align__(16) float g_Zn[(size_t)BMAX * Dc];           // tf32-rounded
__device__ __align__(16) float g_T[(size_t)BMAX * Dc];            // tf32-rounded
__device__ __align__(16) float g_Bv[Dc * Dc];                     // rounded weights
__device__ __align__(16) float g_Bo[Dc * Dc];
__device__ __align__(16) float g_B1[Dc * Dc];
__device__ __align__(16) float g_B2[DOUTc * Dc];

// ---------------- helpers --------------------------------------------------
__device__ __forceinline__ float warp_sum(float v) {
#pragma unroll
    for (int o = 16; o; o >>= 1) v += __shfl_xor_sync(0xffffffffu, v, o);
    return v;
}
__device__ __forceinline__ float warp_max(float v) {
#pragma unroll
    for (int o = 16; o; o >>= 1) v = fmaxf(v, __shfl_xor_sync(0xffffffffu, v, o));
    return v;
}
__device__ __forceinline__ float tf32r(float f) {
    uint32_t r;
    asm("cvt.rna.tf32.f32 %0, %1;" : "=r"(r) : "f"(f));
    return __uint_as_float(r);
}
__device__ __forceinline__ void mma_tf32(float& c0, float& c1, float& c2, float& c3,
                                         float a0, float a1, float a2, float a3,
                                         float b0, float b1) {
    asm volatile(
        "mma.sync.aligned.m16n8k8.row.col.f32.tf32.tf32.f32 "
        "{%0,%1,%2,%3}, {%4,%5,%6,%7}, {%8,%9}, {%0,%1,%2,%3};"
        : "+f"(c0), "+f"(c1), "+f"(c2), "+f"(c3)
        : "r"(__float_as_uint(a0)), "r"(__float_as_uint(a1)),
          "r"(__float_as_uint(a2)), "r"(__float_as_uint(a3)),
          "r"(__float_as_uint(b0)), "r"(__float_as_uint(b1)));
}

// ---------------- setup 1: qvec = Wq.agg + bq ; cbias = opb + Wo.bv -------
__global__ void k_setup1(const float* __restrict__ agg,
                         const float* __restrict__ ipw,
                         const float* __restrict__ ipb,
                         const float* __restrict__ opw,
                         const float* __restrict__ opb) {
    __shared__ float red[4];
    const int d = blockIdx.x;
    const int t = threadIdx.x;
    const int lane = t & 31, wid = t >> 5;
    const bool isq = d < Dc;
    const float* row = isq ? (ipw + (size_t)d * Dc) : (opw + (size_t)(d - Dc) * Dc);
    const float* vec = isq ? agg : (ipb + 2 * Dc);
    float acc = 0.f;
    for (int e = t; e < Dc; e += 128) acc += row[e] * vec[e];
    acc = warp_sum(acc);
    if (lane == 0) red[wid] = acc;
    __syncthreads();
    if (t == 0) {
        float s = red[0] + red[1] + red[2] + red[3];
        if (isq) g_qvec[d] = s + ipb[d];
        else     g_cbias[d - Dc] = s + opb[d - Dc];
    }
}

// ---------------- setup 2: qk[h,e] = sum_hd qvec[h*64+hd] * Wk[h*64+hd,e] -
__global__ void k_setup2(const float* __restrict__ ipw) {
    const int idx = blockIdx.x * 256 + threadIdx.x;
    const int h = idx >> 9, e = idx & 511;
    const float* base = ipw + (size_t)(Dc + h * 64) * Dc + e;
    float acc = 0.f;
#pragma unroll 16
    for (int hd = 0; hd < 64; ++hd)
        acc += g_qvec[h * 64 + hd] * base[(size_t)hd * Dc];
    g_qk[idx] = acc;
}

// ---------------- tf32 rounding copy ---------------------------------------
__global__ void k_round(const float* __restrict__ s, float* __restrict__ d, int n) {
    for (int i = blockIdx.x * 256 + threadIdx.x; i < n; i += gridDim.x * 256)
        d[i] = tf32r(s[i]);
}

// ---------------- attention: scores/softmax/9 weighted sums ----------------
__global__ __launch_bounds__(256) void k_attn(const float* __restrict__ H,
                                              const float* __restrict__ w) {
    __shared__ __align__(16) float s_aw[64][12];  // [m][0..7]=attn, [8]=w
    const int b = blockIdx.x, t = threadIdx.x;
    const int lane = t & 31, wid = t >> 5;
    const float* Hb = H + (size_t)b * Mc * Dc;

    if (t < Mc) s_aw[t][8] = w[b * Mc + t];

    // qk for head `wid` in registers
    float4 qv[4];
    {
        const float4* qp = (const float4*)(g_qk + wid * Dc + lane * 16);
        qv[0] = qp[0]; qv[1] = qp[1]; qv[2] = qp[2]; qv[3] = qp[3];
    }
    // scores: warp wid = head wid, all 64 rows
#pragma unroll 1
    for (int m = 0; m < Mc; ++m) {
        const float4* hp = (const float4*)(Hb + m * Dc + lane * 16);
        const float4 h0 = hp[0], h1 = hp[1], h2 = hp[2], h3 = hp[3];
        float a = qv[0].x * h0.x;
        a = fmaf(qv[0].y, h0.y, a); a = fmaf(qv[0].z, h0.z, a); a = fmaf(qv[0].w, h0.w, a);
        a = fmaf(qv[1].x, h1.x, a); a = fmaf(qv[1].y, h1.y, a);
        a = fmaf(qv[1].z, h1.z, a); a = fmaf(qv[1].w, h1.w, a);
        a = fmaf(qv[2].x, h2.x, a); a = fmaf(qv[2].y, h2.y, a);
        a = fmaf(qv[2].z, h2.z, a); a = fmaf(qv[2].w, h2.w, a);
        a = fmaf(qv[3].x, h3.x, a); a = fmaf(qv[3].y, h3.y, a);
        a = fmaf(qv[3].z, h3.z, a); a = fmaf(qv[3].w, h3.w, a);
        a = warp_sum(a);
        if (lane == 0) s_aw[m][wid] = a * 0.125f;
    }
    __syncthreads();

    // softmax: warp wid handles head wid
    {
        float v0 = s_aw[lane][wid], v1 = s_aw[lane + 32][wid];
        float mx = warp_max(fmaxf(v0, v1));
        float e0 = __expf(v0 - mx), e1 = __expf(v1 - mx);
        float inv = 1.0f / warp_sum(e0 + e1);
        s_aw[lane][wid] = e0 * inv;
        s_aw[lane + 32][wid] = e1 * inv;
    }
    __syncthreads();

    // 9 weighted sums: thread t handles cols 2t, 2t+1
    const int d0 = t * 2;
    float u0x = 0.f, u0y = 0.f;
    float ux[NHc], uy[NHc];
#pragma unroll
    for (int h = 0; h < NHc; ++h) { ux[h] = 0.f; uy[h] = 0.f; }
#pragma unroll 4
    for (int m = 0; m < Mc; ++m) {
        const float2 hv = *(const float2*)(Hb + m * Dc + d0);
        const float4 a0 = *(const float4*)(&s_aw[m][0]);
        const float4 a1 = *(const float4*)(&s_aw[m][4]);
        const float wm = s_aw[m][8];
        u0x = fmaf(wm, hv.x, u0x); u0y = fmaf(wm, hv.y, u0y);
        ux[0] = fmaf(a0.x, hv.x, ux[0]); uy[0] = fmaf(a0.x, hv.y, uy[0]);
        ux[1] = fmaf(a0.y, hv.x, ux[1]); uy[1] = fmaf(a0.y, hv.y, uy[1]);
        ux[2] = fmaf(a0.z, hv.x, ux[2]); uy[2] = fmaf(a0.z, hv.y, uy[2]);
        ux[3] = fmaf(a0.w, hv.x, ux[3]); uy[3] = fmaf(a0.w, hv.y, uy[3]);
        ux[4] = fmaf(a1.x, hv.x, ux[4]); uy[4] = fmaf(a1.x, hv.y, uy[4]);
        ux[5] = fmaf(a1.y, hv.x, ux[5]); uy[5] = fmaf(a1.y, hv.y, uy[5]);
        ux[6] = fmaf(a1.z, hv.x, ux[6]); uy[6] = fmaf(a1.z, hv.y, uy[6]);
        ux[7] = fmaf(a1.w, hv.x, ux[7]); uy[7] = fmaf(a1.w, hv.y, uy[7]);
    }
    *(float2*)(g_Z + (size_t)b * Dc + d0) = make_float2(u0x, u0y);
#pragma unroll
    for (int h = 0; h < NHc; ++h) {
        *(float2*)(g_Uattn + ((size_t)b * NHc + h) * Dc + d0) =
            make_float2(tf32r(ux[h]), tf32r(uy[h]));
    }
}

// ---------------- mma.sync tf32 GEMM: C[128x64] = A @ B^T + epilogue -------
// Block: 256 thr = 8 warps (4m x 2n), warp tile 32x32, K-chunk 32, dbl-buffer.
// Smem k-permuted: col c stored at (c%4)*8 + c/4  -> fragment LDS.128 gathers.
// MODE 0: CTX = Uattn(b,h) @ Wv_h^T          MODE 1: Z += CTX @ Wo^T + cbias
// MODE 2: T = tf32(gelu(Zn @ W1^T + b1))     MODE 3: OUT = T @ W2^T + b2
#define APITCH 36
#define ABUF (128 * APITCH)
#define BBUF (64 * APITCH)
template <int MODE>
__global__ __launch_bounds__(256) void k_gemm_mma(const float* __restrict__ Bw,
                                                  const float* __restrict__ bias,
                                                  float* __restrict__ outp) {
    extern __shared__ float sm[];
    float* As = sm;                 // [2][128][36]
    float* Bs = sm + 2 * ABUF;      // [2][64][36]
    const int t = threadIdx.x, lane = t & 31, wid = t >> 5;
    const int gid = lane >> 2, tig = lane & 3;
    const int wm = wid >> 1, wn = wid & 1;
    const int bb = blockIdx.x, jb = blockIdx.y;

    const float* A = (MODE == 0) ? g_Uattn
                   : (MODE == 1) ? g_CTX
                   : (MODE == 2) ? g_Zn : g_T;

    // gmem load slots (float4 each): A 4/thread, B 2/thread
    const float* aptr[4]; int arowv[4], asegv[4];
#pragma unroll
    for (int i = 0; i < 4; ++i) {
        const int f = t + i * 256, r = f >> 3, seg = f & 7;
        const size_t arow = (MODE == 0)
            ? ((size_t)(bb * 128 + r) * NHc + jb) * Dc
            : (size_t)(bb * 128 + r) * Dc;
        aptr[i] = A + arow + seg * 4;
        arowv[i] = r; asegv[i] = seg;
    }
    const float* bptr[2]; int browv[2], bsegv[2];
#pragma unroll
    for (int i = 0; i < 2; ++i) {
        const int f = t + i * 256, r = f >> 3, seg = f & 7;
        bptr[i] = Bw + (size_t)(jb * 64 + r) * Dc + seg * 4;
        browv[i] = r; bsegv[i] = seg;
    }

    float4 ar[4], br[2];
    auto ldg = [&](int kc) {
#pragma unroll
        for (int i = 0; i < 4; ++i) ar[i] = *(const float4*)(aptr[i] + kc * 32);
#pragma unroll
        for (int i = 0; i < 2; ++i) br[i] = *(const float4*)(bptr[i] + kc * 32);
    };
    auto sts = [&](int buf) {
#pragma unroll
        for (int i = 0; i < 4; ++i) {
            float* dst = As + buf * ABUF + arowv[i] * APITCH;
            const int s = asegv[i];
            dst[0 * 8 + s] = ar[i].x; dst[1 * 8 + s] = ar[i].y;
            dst[2 * 8 + s] = ar[i].z; dst[3 * 8 + s] = ar[i].w;
        }
#pragma unroll
        for (int i = 0; i < 2; ++i) {
            float* dst = Bs + buf * BBUF + browv[i] * APITCH;
            const int s = bsegv[i];
            dst[0 * 8 + s] = br[i].x; dst[1 * 8 + s] = br[i].y;
            dst[2 * 8 + s] = br[i].z; dst[3 * 8 + s] = br[i].w;
        }
    };

    float acc[2][4][4];
#pragma unroll
    for (int mi = 0; mi < 2; ++mi)
#pragma unroll
        for (int ni = 0; ni < 4; ++ni)
#pragma unroll
            for (int q = 0; q < 4; ++q) acc[mi][ni][q] = 0.f;

    auto compute = [&](int buf) {
        const float* as = As + buf * ABUF;
        const float* bs = Bs + buf * BBUF;
#pragma unroll
        for (int half = 0; half < 2; ++half) {
            float4 af[2][2];
#pragma unroll
            for (int mi = 0; mi < 2; ++mi)
#pragma unroll
                for (int p = 0; p < 2; ++p)
                    af[mi][p] = *(const float4*)(as +
                        (wm * 32 + mi * 16 + gid + p * 8) * APITCH + tig * 8 + half * 4);
            float4 bf[4];
#pragma unroll
            for (int ni = 0; ni < 4; ++ni)
                bf[ni] = *(const float4*)(bs +
                    (wn * 32 + ni * 8 + gid) * APITCH + tig * 8 + half * 4);
#pragma unroll
            for (int ks2 = 0; ks2 < 2; ++ks2) {
#pragma unroll
                for (int mi = 0; mi < 2; ++mi) {
                    const float a0 = ks2 ? af[mi][0].z : af[mi][0].x;
                    const float a1 = ks2 ? af[mi][1].z : af[mi][1].x;
                    const float a2 = ks2 ? af[mi][0].w : af[mi][0].y;
                    const float a3 = ks2 ? af[mi][1].w : af[mi][1].y;
#pragma unroll
                    for (int ni = 0; ni < 4; ++ni) {
                        const float b0 = ks2 ? bf[ni].z : bf[ni].x;
                        const float b1 = ks2 ? bf[ni].w : bf[ni].y;
                        mma_tf32(acc[mi][ni][0], acc[mi][ni][1],
                                 acc[mi][ni][2], acc[mi][ni][3],
                                 a0, a1, a2, a3, b0, b1);
                    }
                }
            }
        }
    };

    ldg(0); sts(0); __syncthreads();
#pragma unroll 1
    for (int kc = 0; kc < 16; ++kc) {
        if (kc + 1 < 16) ldg(kc + 1);
        compute(kc & 1);
        if (kc + 1 < 16) {
            __syncthreads();
            sts((kc + 1) & 1);
            __syncthreads();
        }
    }

    // epilogue: C[row][col]; fragment c0..c3 = (gid, 2tig),(gid,2tig+1),(gid+8,..)
    const int row0 = bb * 128 + wm * 32;
    const int col0 = jb * 64 + wn * 32;
#pragma unroll
    for (int mi = 0; mi < 2; ++mi) {
#pragma unroll
        for (int p = 0; p < 2; ++p) {
            const int row = row0 + mi * 16 + gid + p * 8;
#pragma unroll
            for (int ni = 0; ni < 4; ++ni) {
                const int col = col0 + ni * 8 + tig * 2;
                float v0 = acc[mi][ni][p * 2 + 0];
                float v1 = acc[mi][ni][p * 2 + 1];
                if (MODE == 0) {
                    *(float2*)(g_CTX + (size_t)row * Dc + col) =
                        make_float2(tf32r(v0), tf32r(v1));
                } else if (MODE == 1) {
                    float* zp = g_Z + (size_t)row * Dc + col;
                    float2 z = *(float2*)zp;
                    *(float2*)zp = make_float2(z.x + v0 + g_cbias[col],
                                               z.y + v1 + g_cbias[col + 1]);
                } else if (MODE == 2) {
                    v0 += bias[col]; v1 += bias[col + 1];
                    v0 = 0.5f * v0 * (1.0f + erff(v0 * 0.70710678118654752f));
                    v1 = 0.5f * v1 * (1.0f + erff(v1 * 0.70710678118654752f));
                    *(float2*)(g_T + (size_t)row * Dc + col) =
                        make_float2(tf32r(v0), tf32r(v1));
                } else {
                    v0 += bias[col]; v1 += bias[col + 1];
                    if (v0 != v0) v0 = 0.f;
                    if (v1 != v1) v1 = 0.f;
                    *(float2*)(outp + (size_t)row * DOUTc + col) = make_float2(v0, v1);
                }
            }
        }
    }
}

// ---------------- row LayerNorm over g_Z -> g_Zn (tf32-rounded) ------------
__global__ __launch_bounds__(128) void k_ln(const float* __restrict__ gamma,
                                            const float* __restrict__ beta) {
    __shared__ float rs[4], rss[4];
    __shared__ float s_mu, s_inv;
    const int b = blockIdx.x, t = threadIdx.x;
    const int lane = t & 31, wid = t >> 5;
    const float* z = g_Z + (size_t)b * Dc;
    float x[4];
#pragma unroll
    for (int i = 0; i < 4; ++i) x[i] = z[t + (i << 7)];
    float s = x[0] + x[1] + x[2] + x[3];
    float ss = x[0] * x[0] + x[1] * x[1] + x[2] * x[2] + x[3] * x[3];
    s = warp_sum(s); ss = warp_sum(ss);
    if (lane == 0) { rs[wid] = s; rss[wid] = ss; }
    __syncthreads();
    if (t == 0) {
        const float S = rs[0] + rs[1] + rs[2] + rs[3];
        const float SS = rss[0] + rss[1] + rss[2] + rss[3];
        const float mu = S * (1.0f / Dc);
        s_mu = mu;
        s_inv = rsqrtf(SS * (1.0f / Dc) - mu * mu + 1e-5f);
    }
    __syncthreads();
    const float mu = s_mu, inv = s_inv;
    float* zn = g_Zn + (size_t)b * Dc;
#pragma unroll
    for (int i = 0; i < 4; ++i) {
        const int d = t + (i << 7);
        zn[d] = tf32r((x[i] - mu) * inv * gamma[d] + beta[d]);
    }
}

// ---------------- launch ----------------------------------------------------
extern "C" void kernel_launch(void* const* d_in, const int* in_sizes, int n_in,
                              void* d_out, int out_size) {
    const float* H   = (const float*)d_in[0];
    const float* w   = (const float*)d_in[1];
    const float* agg = (const float*)d_in[2];
    const float* ipw = (const float*)d_in[3];
    const float* ipb = (const float*)d_in[4];
    const float* opw = (const float*)d_in[5];
    const float* opb = (const float*)d_in[6];
    const float* lng = (const float*)d_in[7];
    const float* lnb = (const float*)d_in[8];
    const float* w1  = (const float*)d_in[9];
    const float* b1  = (const float*)d_in[10];
    const float* w2  = (const float*)d_in[11];
    const float* b2  = (const float*)d_in[12];
    float* outp = (float*)d_out;
    const int Bn = in_sizes[0] / (Mc * Dc);          // 4096
    const int SMB = (2 * ABUF + 2 * BBUF) * 4;       // 55296 B

    cudaFuncSetAttribute(k_gemm_mma<0>, cudaFuncAttributeMaxDynamicSharedMemorySize, SMB);
    cudaFuncSetAttribute(k_gemm_mma<1>, cudaFuncAttributeMaxDynamicSharedMemorySize, SMB);
    cudaFuncSetAttribute(k_gemm_mma<2>, cudaFuncAttributeMaxDynamicSharedMemorySize, SMB);
    cudaFuncSetAttribute(k_gemm_mma<3>, cudaFuncAttributeMaxDynamicSharedMemorySize, SMB);

    float* dBv; float* dBo; float* dB1; float* dB2;
    cudaGetSymbolAddress((void**)&dBv, g_Bv);
    cudaGetSymbolAddress((void**)&dBo, g_Bo);
    cudaGetSymbolAddress((void**)&dB1, g_B1);
    cudaGetSymbolAddress((void**)&dB2, g_B2);

    k_setup1<<<2 * Dc, 128>>>(agg, ipw, ipb, opw, opb);
    k_setup2<<<(NHc * Dc) / 256, 256>>>(ipw);
    k_round<<<256, 256>>>(ipw + 2 * Dc * Dc, dBv, Dc * Dc);
    k_round<<<256, 256>>>(opw, dBo, Dc * Dc);
    k_round<<<256, 256>>>(w1, dB1, Dc * Dc);
    k_round<<<128, 256>>>(w2, dB2, DOUTc * Dc);
    k_attn<<<Bn, 256>>>(H, w);
    k_gemm_mma<0><<<dim3(Bn / 128, NHc), 256, SMB>>>(dBv, nullptr, nullptr);
    k_gemm_mma<1><<<dim3(Bn / 128, Dc / 64), 256, SMB>>>(dBo, nullptr, nullptr);
    k_ln<<<Bn, 128>>>(lng, lnb);
    k_gemm_mma<2><<<dim3(Bn / 128, Dc / 64), 256, SMB>>>(dB1, b1, nullptr);
    k_gemm_mma<3><<<dim3(Bn / 128, DOUTc / 64), 256, SMB>>>(dB2, b2, outp);
}

// round 6
// speedup vs baseline: 1.6399x; 1.6399x over previous
#include <cuda_runtime.h>
#include <math.h>
#include <stdint.h>

#define BMAX 4096
#define Mc   64
#define Dc   512
#define DOUTc 256
#define NHc  8

// ---------------- scratch (device globals; no allocations) ----------------
__device__ __align__(16) float g_qvec[Dc];
__device__ __align__(16) float g_qk[NHc * Dc];
__device__ __align__(16) float g_cbias[Dc];
__device__ __align__(16) float g_Uattn[(size_t)BMAX * NHc * Dc];  // tf32-rounded
__device__ __align__(16) float g_CTX[(size_t)BMAX * Dc];          // tf32-rounded
__device__ __align__(16) float g_Z[(size_t)BMAX * Dc];            // fp32
__device__ __align__(16) float g_Zn[(size_t)BMAX * Dc];           // tf32-rounded
__device__ __align__(16) float g_T[(size_t)BMAX * Dc];            // tf32-rounded
__device__ __align__(16) float g_Bv[Dc * Dc];                     // rounded weights
__device__ __align__(16) float g_Bo[Dc * Dc];
__device__ __align__(16) float g_B1[Dc * Dc];
__device__ __align__(16) float g_B2[DOUTc * Dc];

// ---------------- helpers --------------------------------------------------
__device__ __forceinline__ float warp_sum(float v) {
#pragma unroll
    for (int o = 16; o; o >>= 1) v += __shfl_xor_sync(0xffffffffu, v, o);
    return v;
}
__device__ __forceinline__ float warp_max(float v) {
#pragma unroll
    for (int o = 16; o; o >>= 1) v = fmaxf(v, __shfl_xor_sync(0xffffffffu, v, o));
    return v;
}
__device__ __forceinline__ float tf32r(float f) {
    uint32_t r;
    asm("cvt.rna.tf32.f32 %0, %1;" : "=r"(r) : "f"(f));
    return __uint_as_float(r);
}
__device__ __forceinline__ uint32_t smem_u32(const void* p) {
    uint32_t a;
    asm("{ .reg .u64 t; cvta.to.shared.u64 t, %1; cvt.u32.u64 %0, t; }"
        : "=r"(a) : "l"(p));
    return a;
}
__device__ __forceinline__ void mma_tf32(float& c0, float& c1, float& c2, float& c3,
                                         float a0, float a1, float a2, float a3,
                                         float b0, float b1) {
    asm volatile(
        "mma.sync.aligned.m16n8k8.row.col.f32.tf32.tf32.f32 "
        "{%0,%1,%2,%3}, {%4,%5,%6,%7}, {%8,%9}, {%0,%1,%2,%3};"
        : "+f"(c0), "+f"(c1), "+f"(c2), "+f"(c3)
        : "r"(__float_as_uint(a0)), "r"(__float_as_uint(a1)),
          "r"(__float_as_uint(a2)), "r"(__float_as_uint(a3)),
          "r"(__float_as_uint(b0)), "r"(__float_as_uint(b1)));
}

// ---------------- setup 1: qvec = Wq.agg + bq ; cbias = opb + Wo.bv -------
__global__ void k_setup1(const float* __restrict__ agg,
                         const float* __restrict__ ipw,
                         const float* __restrict__ ipb,
                         const float* __restrict__ opw,
                         const float* __restrict__ opb) {
    __shared__ float red[4];
    const int d = blockIdx.x;
    const int t = threadIdx.x;
    const int lane = t & 31, wid = t >> 5;
    const bool isq = d < Dc;
    const float* row = isq ? (ipw + (size_t)d * Dc) : (opw + (size_t)(d - Dc) * Dc);
    const float* vec = isq ? agg : (ipb + 2 * Dc);
    float acc = 0.f;
    for (int e = t; e < Dc; e += 128) acc += row[e] * vec[e];
    acc = warp_sum(acc);
    if (lane == 0) red[wid] = acc;
    __syncthreads();
    if (t == 0) {
        float s = red[0] + red[1] + red[2] + red[3];
        if (isq) g_qvec[d] = s + ipb[d];
        else     g_cbias[d - Dc] = s + opb[d - Dc];
    }
}

// ---------------- setup 2: qk[h,e] = sum_hd qvec[h*64+hd] * Wk[h*64+hd,e] -
__global__ void k_setup2(const float* __restrict__ ipw) {
    const int idx = blockIdx.x * 256 + threadIdx.x;
    const int h = idx >> 9, e = idx & 511;
    const float* base = ipw + (size_t)(Dc + h * 64) * Dc + e;
    float acc = 0.f;
#pragma unroll 16
    for (int hd = 0; hd < 64; ++hd)
        acc += g_qvec[h * 64 + hd] * base[(size_t)hd * Dc];
    g_qk[idx] = acc;
}

// ---------------- tf32 rounding copy ---------------------------------------
__global__ void k_round(const float* __restrict__ s, float* __restrict__ d, int n) {
    for (int i = blockIdx.x * 256 + threadIdx.x; i < n; i += gridDim.x * 256)
        d[i] = tf32r(s[i]);
}

// ---------------- attention v3: H[b] smem-resident --------------------------
// cp.async stages H[b] (128KB) in 4 chunks; scores overlap loads; weighted
// sums read smem. Scores & weighted math is pure fp32 (no extra rounding).
__global__ __launch_bounds__(256) void k_attn(const float* __restrict__ H,
                                              const float* __restrict__ w) {
    extern __shared__ __align__(16) float Hs[];       // 64 x 512 fp32
    __shared__ __align__(16) float s_aw[64][12];      // [m][0..7]=attn, [8]=w
    const int b = blockIdx.x, t = threadIdx.x;
    const int lane = t & 31, wid = t >> 5;
    const float4* Hb4 = (const float4*)(H + (size_t)b * Mc * Dc);
    const uint32_t hs = smem_u32(Hs);

    if (t < Mc) s_aw[t][8] = w[b * Mc + t];

    // qk for head `wid`, interleaved cols lane*4 + i*128 (conflict-free LDS)
    float4 qv[4];
#pragma unroll
    for (int i = 0; i < 4; ++i)
        qv[i] = *(const float4*)(g_qk + wid * Dc + lane * 4 + i * 128);

    // issue all 4 chunks (16 rows = 2048 float4 each), one commit per chunk
#pragma unroll
    for (int ch = 0; ch < 4; ++ch) {
#pragma unroll
        for (int i = 0; i < 8; ++i) {
            const int f4 = ch * 2048 + t + i * 256;
            asm volatile("cp.async.cg.shared.global [%0], [%1], 16;"
                         :: "r"(hs + f4 * 16), "l"(Hb4 + f4) : "memory");
        }
        asm volatile("cp.async.commit_group;" ::: "memory");
    }

    // ---- scores, chunk by chunk; warp wid = head wid, all rows
#pragma unroll
    for (int ch = 0; ch < 4; ++ch) {
        if (ch == 0)      asm volatile("cp.async.wait_group 3;" ::: "memory");
        else if (ch == 1) asm volatile("cp.async.wait_group 2;" ::: "memory");
        else if (ch == 2) asm volatile("cp.async.wait_group 1;" ::: "memory");
        else              asm volatile("cp.async.wait_group 0;" ::: "memory");
        __syncthreads();
#pragma unroll
        for (int r4 = 0; r4 < 16; r4 += 4) {
            float acc[4];
#pragma unroll
            for (int j = 0; j < 4; ++j) {
                const int m = ch * 16 + r4 + j;
                const float4* hp = (const float4*)(Hs + m * Dc + lane * 4);
                const float4 h0 = hp[0], h1 = hp[32], h2 = hp[64], h3 = hp[96];
                float a = qv[0].x * h0.x;
                a = fmaf(qv[0].y, h0.y, a); a = fmaf(qv[0].z, h0.z, a);
                a = fmaf(qv[0].w, h0.w, a);
                a = fmaf(qv[1].x, h1.x, a); a = fmaf(qv[1].y, h1.y, a);
                a = fmaf(qv[1].z, h1.z, a); a = fmaf(qv[1].w, h1.w, a);
                a = fmaf(qv[2].x, h2.x, a); a = fmaf(qv[2].y, h2.y, a);
                a = fmaf(qv[2].z, h2.z, a); a = fmaf(qv[2].w, h2.w, a);
                a = fmaf(qv[3].x, h3.x, a); a = fmaf(qv[3].y, h3.y, a);
                a = fmaf(qv[3].w, h3.w, fmaf(qv[3].z, h3.z, a));
                acc[j] = a;
            }
#pragma unroll
            for (int j = 0; j < 4; ++j) acc[j] = warp_sum(acc[j]);
            if (lane == 0) {
#pragma unroll
                for (int j = 0; j < 4; ++j)
                    s_aw[ch * 16 + r4 + j][wid] = acc[j] * 0.125f;
            }
        }
    }
    __syncthreads();

    // ---- softmax: warp wid handles head wid
    {
        float v0 = s_aw[lane][wid], v1 = s_aw[lane + 32][wid];
        float mx = warp_max(fmaxf(v0, v1));
        float e0 = __expf(v0 - mx), e1 = __expf(v1 - mx);
        float inv = 1.0f / warp_sum(e0 + e1);
        s_aw[lane][wid] = e0 * inv;
        s_aw[lane + 32][wid] = e1 * inv;
    }
    __syncthreads();

    // ---- 9 weighted sums from smem: thread t handles cols 2t, 2t+1
    const int d0 = t * 2;
    float u0x = 0.f, u0y = 0.f;
    float ux[NHc], uy[NHc];
#pragma unroll
    for (int h = 0; h < NHc; ++h) { ux[h] = 0.f; uy[h] = 0.f; }
#pragma unroll 4
    for (int m = 0; m < Mc; ++m) {
        const float2 hv = *(const float2*)(Hs + m * Dc + d0);
        const float4 a0 = *(const float4*)(&s_aw[m][0]);
        const float4 a1 = *(const float4*)(&s_aw[m][4]);
        const float wm = s_aw[m][8];
        u0x = fmaf(wm, hv.x, u0x); u0y = fmaf(wm, hv.y, u0y);
        ux[0] = fmaf(a0.x, hv.x, ux[0]); uy[0] = fmaf(a0.x, hv.y, uy[0]);
        ux[1] = fmaf(a0.y, hv.x, ux[1]); uy[1] = fmaf(a0.y, hv.y, uy[1]);
        ux[2] = fmaf(a0.z, hv.x, ux[2]); uy[2] = fmaf(a0.z, hv.y, uy[2]);
        ux[3] = fmaf(a0.w, hv.x, ux[3]); uy[3] = fmaf(a0.w, hv.y, uy[3]);
        ux[4] = fmaf(a1.x, hv.x, ux[4]); uy[4] = fmaf(a1.x, hv.y, uy[4]);
        ux[5] = fmaf(a1.y, hv.x, ux[5]); uy[5] = fmaf(a1.y, hv.y, uy[5]);
        ux[6] = fmaf(a1.z, hv.x, ux[6]); uy[6] = fmaf(a1.z, hv.y, uy[6]);
        ux[7] = fmaf(a1.w, hv.x, ux[7]); uy[7] = fmaf(a1.w, hv.y, uy[7]);
    }
    *(float2*)(g_Z + (size_t)b * Dc + d0) = make_float2(u0x, u0y);
#pragma unroll
    for (int h = 0; h < NHc; ++h) {
        *(float2*)(g_Uattn + ((size_t)b * NHc + h) * Dc + d0) =
            make_float2(tf32r(ux[h]), tf32r(uy[h]));
    }
}

// ---------------- mma.sync tf32 GEMM: C[128x64] = A @ B^T + epilogue -------
#define APITCH 36
#define ABUF (128 * APITCH)
#define BBUF (64 * APITCH)
template <int MODE>
__global__ __launch_bounds__(256) void k_gemm_mma(const float* __restrict__ Bw,
                                                  const float* __restrict__ bias,
                                                  float* __restrict__ outp) {
    extern __shared__ float sm[];
    float* As = sm;                 // [2][128][36]
    float* Bs = sm + 2 * ABUF;      // [2][64][36]
    const int t = threadIdx.x, lane = t & 31, wid = t >> 5;
    const int gid = lane >> 2, tig = lane & 3;
    const int wm = wid >> 1, wn = wid & 1;
    const int bb = blockIdx.x, jb = blockIdx.y;

    const float* A = (MODE == 0) ? g_Uattn
                   : (MODE == 1) ? g_CTX
                   : (MODE == 2) ? g_Zn : g_T;

    const float* aptr[4]; int arowv[4], asegv[4];
#pragma unroll
    for (int i = 0; i < 4; ++i) {
        const int f = t + i * 256, r = f >> 3, seg = f & 7;
        const size_t arow = (MODE == 0)
            ? ((size_t)(bb * 128 + r) * NHc + jb) * Dc
            : (size_t)(bb * 128 + r) * Dc;
        aptr[i] = A + arow + seg * 4;
        arowv[i] = r; asegv[i] = seg;
    }
    const float* bptr[2]; int browv[2], bsegv[2];
#pragma unroll
    for (int i = 0; i < 2; ++i) {
        const int f = t + i * 256, r = f >> 3, seg = f & 7;
        bptr[i] = Bw + (size_t)(jb * 64 + r) * Dc + seg * 4;
        browv[i] = r; bsegv[i] = seg;
    }

    float4 ar[4], br[2];
    auto ldg = [&](int kc) {
#pragma unroll
        for (int i = 0; i < 4; ++i) ar[i] = *(const float4*)(aptr[i] + kc * 32);
#pragma unroll
        for (int i = 0; i < 2; ++i) br[i] = *(const float4*)(bptr[i] + kc * 32);
    };
    auto sts = [&](int buf) {
#pragma unroll
        for (int i = 0; i < 4; ++i) {
            float* dst = As + buf * ABUF + arowv[i] * APITCH;
            const int s = asegv[i];
            dst[0 * 8 + s] = ar[i].x; dst[1 * 8 + s] = ar[i].y;
            dst[2 * 8 + s] = ar[i].z; dst[3 * 8 + s] = ar[i].w;
        }
#pragma unroll
        for (int i = 0; i < 2; ++i) {
            float* dst = Bs + buf * BBUF + browv[i] * APITCH;
            const int s = bsegv[i];
            dst[0 * 8 + s] = br[i].x; dst[1 * 8 + s] = br[i].y;
            dst[2 * 8 + s] = br[i].z; dst[3 * 8 + s] = br[i].w;
        }
    };

    float acc[2][4][4];
#pragma unroll
    for (int mi = 0; mi < 2; ++mi)
#pragma unroll
        for (int ni = 0; ni < 4; ++ni)
#pragma unroll
            for (int q = 0; q < 4; ++q) acc[mi][ni][q] = 0.f;

    auto compute = [&](int buf) {
        const float* as = As + buf * ABUF;
        const float* bs = Bs + buf * BBUF;
#pragma unroll
        for (int half = 0; half < 2; ++half) {
            float4 af[2][2];
#pragma unroll
            for (int mi = 0; mi < 2; ++mi)
#pragma unroll
                for (int p = 0; p < 2; ++p)
                    af[mi][p] = *(const float4*)(as +
                        (wm * 32 + mi * 16 + gid + p * 8) * APITCH + tig * 8 + half * 4);
            float4 bf[4];
#pragma unroll
            for (int ni = 0; ni < 4; ++ni)
                bf[ni] = *(const float4*)(bs +
                    (wn * 32 + ni * 8 + gid) * APITCH + tig * 8 + half * 4);
#pragma unroll
            for (int ks2 = 0; ks2 < 2; ++ks2) {
#pragma unroll
                for (int mi = 0; mi < 2; ++mi) {
                    const float a0 = ks2 ? af[mi][0].z : af[mi][0].x;
                    const float a1 = ks2 ? af[mi][1].z : af[mi][1].x;
                    const float a2 = ks2 ? af[mi][0].w : af[mi][0].y;
                    const float a3 = ks2 ? af[mi][1].w : af[mi][1].y;
#pragma unroll
                    for (int ni = 0; ni < 4; ++ni) {
                        const float b0 = ks2 ? bf[ni].z : bf[ni].x;
                        const float b1 = ks2 ? bf[ni].w : bf[ni].y;
                        mma_tf32(acc[mi][ni][0], acc[mi][ni][1],
                                 acc[mi][ni][2], acc[mi][ni][3],
                                 a0, a1, a2, a3, b0, b1);
                    }
                }
            }
        }
    };

    ldg(0); sts(0); __syncthreads();
#pragma unroll 1
    for (int kc = 0; kc < 16; ++kc) {
        if (kc + 1 < 16) ldg(kc + 1);
        compute(kc & 1);
        if (kc + 1 < 16) {
            __syncthreads();
            sts((kc + 1) & 1);
            __syncthreads();
        }
    }

    const int row0 = bb * 128 + wm * 32;
    const int col0 = jb * 64 + wn * 32;
#pragma unroll
    for (int mi = 0; mi < 2; ++mi) {
#pragma unroll
        for (int p = 0; p < 2; ++p) {
            const int row = row0 + mi * 16 + gid + p * 8;
#pragma unroll
            for (int ni = 0; ni < 4; ++ni) {
                const int col = col0 + ni * 8 + tig * 2;
                float v0 = acc[mi][ni][p * 2 + 0];
                float v1 = acc[mi][ni][p * 2 + 1];
                if (MODE == 0) {
                    *(float2*)(g_CTX + (size_t)row * Dc + col) =
                        make_float2(tf32r(v0), tf32r(v1));
                } else if (MODE == 1) {
                    float* zp = g_Z + (size_t)row * Dc + col;
                    float2 z = *(float2*)zp;
                    *(float2*)zp = make_float2(z.x + v0 + g_cbias[col],
                                               z.y + v1 + g_cbias[col + 1]);
                } else if (MODE == 2) {
                    v0 += bias[col]; v1 += bias[col + 1];
                    v0 = 0.5f * v0 * (1.0f + erff(v0 * 0.70710678118654752f));
                    v1 = 0.5f * v1 * (1.0f + erff(v1 * 0.70710678118654752f));
                    *(float2*)(g_T + (size_t)row * Dc + col) =
                        make_float2(tf32r(v0), tf32r(v1));
                } else {
                    v0 += bias[col]; v1 += bias[col + 1];
                    if (v0 != v0) v0 = 0.f;
                    if (v1 != v1) v1 = 0.f;
                    *(float2*)(outp + (size_t)row * DOUTc + col) = make_float2(v0, v1);
                }
            }
        }
    }
}

// ---------------- row LayerNorm over g_Z -> g_Zn (tf32-rounded) ------------
__global__ __launch_bounds__(128) void k_ln(const float* __restrict__ gamma,
                                            const float* __restrict__ beta) {
    __shared__ float rs[4], rss[4];
    __shared__ float s_mu, s_inv;
    const int b = blockIdx.x, t = threadIdx.x;
    const int lane = t & 31, wid = t >> 5;
    const float* z = g_Z + (size_t)b * Dc;
    float x[4];
#pragma unroll
    for (int i = 0; i < 4; ++i) x[i] = z[t + (i << 7)];
    float s = x[0] + x[1] + x[2] + x[3];
    float ss = x[0] * x[0] + x[1] * x[1] + x[2] * x[2] + x[3] * x[3];
    s = warp_sum(s); ss = warp_sum(ss);
    if (lane == 0) { rs[wid] = s; rss[wid] = ss; }
    __syncthreads();
    if (t == 0) {
        const float S = rs[0] + rs[1] + rs[2] + rs[3];
        const float SS = rss[0] + rss[1] + rss[2] + rss[3];
        const float mu = S * (1.0f / Dc);
        s_mu = mu;
        s_inv = rsqrtf(SS * (1.0f / Dc) - mu * mu + 1e-5f);
    }
    __syncthreads();
    const float mu = s_mu, inv = s_inv;
    float* zn = g_Zn + (size_t)b * Dc;
#pragma unroll
    for (int i = 0; i < 4; ++i) {
        const int d = t + (i << 7);
        zn[d] = tf32r((x[i] - mu) * inv * gamma[d] + beta[d]);
    }
}

// ---------------- launch ----------------------------------------------------
extern "C" void kernel_launch(void* const* d_in, const int* in_sizes, int n_in,
                              void* d_out, int out_size) {
    const float* H   = (const float*)d_in[0];
    const float* w   = (const float*)d_in[1];
    const float* agg = (const float*)d_in[2];
    const float* ipw = (const float*)d_in[3];
    const float* ipb = (const float*)d_in[4];
    const float* opw = (const float*)d_in[5];
    const float* opb = (const float*)d_in[6];
    const float* lng = (const float*)d_in[7];
    const float* lnb = (const float*)d_in[8];
    const float* w1  = (const float*)d_in[9];
    const float* b1  = (const float*)d_in[10];
    const float* w2  = (const float*)d_in[11];
    const float* b2  = (const float*)d_in[12];
    float* outp = (float*)d_out;
    const int Bn = in_sizes[0] / (Mc * Dc);          // 4096
    const int SMB = (2 * ABUF + 2 * BBUF) * 4;       // 55296 B
    const int SMA = 64 * Dc * 4;                     // 131072 B for k_attn

    cudaFuncSetAttribute(k_attn, cudaFuncAttributeMaxDynamicSharedMemorySize, SMA);
    cudaFuncSetAttribute(k_gemm_mma<0>, cudaFuncAttributeMaxDynamicSharedMemorySize, SMB);
    cudaFuncSetAttribute(k_gemm_mma<1>, cudaFuncAttributeMaxDynamicSharedMemorySize, SMB);
    cudaFuncSetAttribute(k_gemm_mma<2>, cudaFuncAttributeMaxDynamicSharedMemorySize, SMB);
    cudaFuncSetAttribute(k_gemm_mma<3>, cudaFuncAttributeMaxDynamicSharedMemorySize, SMB);

    float* dBv; float* dBo; float* dB1; float* dB2;
    cudaGetSymbolAddress((void**)&dBv, g_Bv);
    cudaGetSymbolAddress((void**)&dBo, g_Bo);
    cudaGetSymbolAddress((void**)&dB1, g_B1);
    cudaGetSymbolAddress((void**)&dB2, g_B2);

    // launch order chosen so the ncu capture (-s 5 -c 1) profiles k_attn (6th)
    k_round<<<256, 256>>>(ipw + 2 * Dc * Dc, dBv, Dc * Dc);   // 1
    k_round<<<256, 256>>>(opw, dBo, Dc * Dc);                 // 2
    k_round<<<256, 256>>>(w1, dB1, Dc * Dc);                  // 3
    k_setup1<<<2 * Dc, 128>>>(agg, ipw, ipb, opw, opb);       // 4
    k_setup2<<<(NHc * Dc) / 256, 256>>>(ipw);                 // 5
    k_attn<<<Bn, 256, SMA>>>(H, w);                           // 6  <- profiled
    k_round<<<128, 256>>>(w2, dB2, DOUTc * Dc);               // 7
    k_gemm_mma<0><<<dim3(Bn / 128, NHc), 256, SMB>>>(dBv, nullptr, nullptr);
    k_gemm_mma<1><<<dim3(Bn / 128, Dc / 64), 256, SMB>>>(dBo, nullptr, nullptr);
    k_ln<<<Bn, 128>>>(lng, lnb);
    k_gemm_mma<2><<<dim3(Bn / 128, Dc / 64), 256, SMB>>>(dB1, b1, nullptr);
    k_gemm_mma<3><<<dim3(Bn / 128, DOUTc / 64), 256, SMB>>>(dB2, b2, outp);
}